// round 8
// baseline (speedup 1.0000x reference)
#include <cuda_runtime.h>
#include <cuda_bf16.h>
#include <math.h>
#include <stdint.h>

// ---------------- problem constants ----------------------------------------
#define T_TOK 4096
#define D_DIM 1024
#define E_NUM 8
#define W_DIM 1024
#define SLOTS 8192          // T*2 (top-2)
#define K3    3072          // concatenated K: A=[hi|hi|lo], B=[hi|lo|hi]
#define BK    32
#define NCH   (K3 / BK)     // 96
#define SAS   40            // smem row stride (bf16) -> conflict-free frag LDS

// ---------------- device scratch --------------------------------------------
__device__ int   g_count[E_NUM];
__device__ int   g_fill [E_NUM];
__device__ int   g_off  [E_NUM + 1];
__device__ int   g_sel  [T_TOK * 2];
__device__ float g_selw [T_TOK * 2];
__device__ int   g_tok  [SLOTS];
__device__ float g_wt   [SLOTS];
__device__ __nv_bfloat16 g_xcat [(size_t)T_TOK * K3];          // 25 MB
__device__ __nv_bfloat16 g_w1cat[(size_t)E_NUM * W_DIM * K3];  // 50 MB [e][n][k]
__device__ __nv_bfloat16 g_w2cat[(size_t)E_NUM * D_DIM * K3];  // 50 MB [e][d][k]
__device__ __nv_bfloat16 g_acat [(size_t)SLOTS * K3];          // 50 MB [slot][k]

// ---------------- small kernels ---------------------------------------------
__global__ void zero_kernel(float* __restrict__ out) {
    int i = blockIdx.x * blockDim.x + threadIdx.x;
    if (i < T_TOK * D_DIM) out[i] = 0.0f;
    if (i < E_NUM) { g_count[i] = 0; g_fill[i] = 0; }
}

__global__ void router_kernel(const float* __restrict__ x, const float* __restrict__ rw) {
    int warp = (blockIdx.x * blockDim.x + threadIdx.x) >> 5;
    int lane = threadIdx.x & 31;
    if (warp >= T_TOK) return;
    const float* xr = x + (size_t)warp * D_DIM;
    float p[E_NUM];
#pragma unroll
    for (int e = 0; e < E_NUM; e++) p[e] = 0.0f;
    for (int d = lane; d < D_DIM; d += 32) {
        float xv = xr[d];
#pragma unroll
        for (int e = 0; e < E_NUM; e++) p[e] += xv * rw[e * D_DIM + d];
    }
#pragma unroll
    for (int e = 0; e < E_NUM; e++)
#pragma unroll
        for (int o = 16; o; o >>= 1) p[e] += __shfl_xor_sync(0xffffffffu, p[e], o);
    if (lane == 0) {
        int i1 = 0; float v1 = p[0];
#pragma unroll
        for (int e = 1; e < E_NUM; e++) if (p[e] > v1) { v1 = p[e]; i1 = e; }
        int i2 = -1; float v2 = -3.0e38f;
#pragma unroll
        for (int e = 0; e < E_NUM; e++) if (e != i1 && p[e] > v2) { v2 = p[e]; i2 = e; }
        float p1 = 1.0f / (1.0f + expf(-v1));
        float p2 = 1.0f / (1.0f + expf(-v2));
        float s = p1 + p2 + 1e-20f;
        g_sel [warp * 2 + 0] = i1;  g_sel [warp * 2 + 1] = i2;
        g_selw[warp * 2 + 0] = p1 / s;
        g_selw[warp * 2 + 1] = p2 / s;
        atomicAdd(&g_count[i1], 1);
        atomicAdd(&g_count[i2], 1);
    }
}

__global__ void offsets_kernel() {
    if (threadIdx.x == 0 && blockIdx.x == 0) {
        int s = 0;
#pragma unroll
        for (int e = 0; e < E_NUM; e++) { g_off[e] = s; s += g_count[e]; }
        g_off[E_NUM] = s;
    }
}

__global__ void fill_kernel() {
    int t = blockIdx.x * blockDim.x + threadIdx.x;
    if (t >= T_TOK) return;
#pragma unroll
    for (int k = 0; k < 2; k++) {
        int e = g_sel[t * 2 + k];
        int pos = g_off[e] + atomicAdd(&g_fill[e], 1);
        g_tok[pos] = t;
        g_wt [pos] = g_selw[t * 2 + k];
    }
}

// x -> [hi | hi | lo] bf16, row-major [T][3072]
__global__ void convert_x(const float* __restrict__ x) {
    int i = blockIdx.x * blockDim.x + threadIdx.x;
    if (i >= T_TOK * D_DIM) return;
    int t = i >> 10, d = i & 1023;
    float v = x[i];
    __nv_bfloat16 hi = __float2bfloat16(v);
    __nv_bfloat16 lo = __float2bfloat16(v - __bfloat162float(hi));
    size_t b = (size_t)t * K3;
    g_xcat[b + d] = hi; g_xcat[b + 1024 + d] = hi; g_xcat[b + 2048 + d] = lo;
}

// Per-expert 1024x1024 transpose + split: dst[e][n][k-seg], segs [hi|lo|hi]
// sel: 0 -> w1 (src_ld=8192, col offset e*1024), 1 -> w2 (src_ld=1024, row offset e*1024)
__global__ void convert_w(const float* __restrict__ src, int sel) {
    __shared__ float tile[32][33];
    int e = blockIdx.z;
    int r0 = blockIdx.y * 32, c0 = blockIdx.x * 32;
    int src_ld  = sel ? 1024 : 8192;
    int row_off = sel ? e * 1024 : 0;
    int col_off = sel ? 0 : e * 1024;
    const float* s = src + (size_t)(row_off + r0) * src_ld + col_off + c0;
#pragma unroll
    for (int i = threadIdx.y; i < 32; i += 8)
        tile[i][threadIdx.x] = s[(size_t)i * src_ld + threadIdx.x];
    __syncthreads();
    __nv_bfloat16* d = (sel ? g_w2cat : g_w1cat) + (size_t)e * 1024 * K3;
#pragma unroll
    for (int i = threadIdx.y; i < 32; i += 8) {
        int c = c0 + i;               // dst row (N index)
        int r = r0 + threadIdx.x;     // dst col (K index)
        float v = tile[threadIdx.x][i];
        __nv_bfloat16 hi = __float2bfloat16(v);
        __nv_bfloat16 lo = __float2bfloat16(v - __bfloat162float(hi));
        size_t bi = (size_t)c * K3 + r;
        d[bi] = hi; d[bi + 1024] = lo; d[bi + 2048] = hi;
    }
}

// ---------------- mma.sync helper -------------------------------------------
__device__ __forceinline__ void mma16816(float* d, const uint32_t* a, const uint32_t* b) {
    asm volatile(
        "mma.sync.aligned.m16n8k16.row.col.f32.bf16.bf16.f32 "
        "{%0,%1,%2,%3}, {%4,%5,%6,%7}, {%8,%9}, {%0,%1,%2,%3};"
        : "+f"(d[0]), "+f"(d[1]), "+f"(d[2]), "+f"(d[3])
        : "r"(a[0]), "r"(a[1]), "r"(a[2]), "r"(a[3]), "r"(b[0]), "r"(b[1]));
}

// ---------------- grouped GEMM (HMMA via mma.sync, bf16x3) -------------------
// MODE 0: up-proj  (A = g_xcat gathered by token, B = g_w1cat, epi -> g_acat split)
// MODE 1: down-proj(A = g_acat by slot,          B = g_w2cat, epi -> atomicAdd out)
template <int MODE>
__global__ void __launch_bounds__(256, 2) moe_gemm(float* __restrict__ out) {
    __shared__ __nv_bfloat16 As[2][128][SAS];
    __shared__ __nv_bfloat16 Bs[2][128][SAS];
    __shared__ int   tok_s[128];
    __shared__ float wt_s [128];

    int e = blockIdx.z;
    int cnt = g_count[e];
    int m0 = blockIdx.y * 128;
    if (m0 >= cnt) return;
    int base = g_off[e];
    int n0 = blockIdx.x * 128;

    int tid = threadIdx.x, lane = tid & 31, wid = tid >> 5;
    int wm = wid & 1, wn = wid >> 1;        // warp grid 2 x 4 -> 64 x 32 per warp
    int g = lane >> 2, tig = lane & 3;

    if (tid < 128) {
        int slot = base + m0 + tid; if (slot >= SLOTS) slot = SLOTS - 1;
        tok_s[tid] = g_tok[slot];
        wt_s [tid] = g_wt[slot];
    }
    __syncthreads();

    const __nv_bfloat16* Acat = MODE ? g_acat : g_xcat;
    const __nv_bfloat16* Bexp = (MODE ? g_w2cat : g_w1cat) + (size_t)e * 1024 * K3;

    // global load assignment: 512 uint4 per tile, 2 per thread
    int arow0 = tid >> 2, arow1 = arow0 + 64;
    int aseg  = (tid & 3) * 8;
    size_t Ar0, Ar1;
    if (MODE == 0) {
        Ar0 = (size_t)tok_s[arow0] * K3 + aseg;
        Ar1 = (size_t)tok_s[arow1] * K3 + aseg;
    } else {
        int s0 = base + m0 + arow0; if (s0 >= SLOTS) s0 = SLOTS - 1;
        int s1 = base + m0 + arow1; if (s1 >= SLOTS) s1 = SLOTS - 1;
        Ar0 = (size_t)s0 * K3 + aseg;
        Ar1 = (size_t)s1 * K3 + aseg;
    }
    size_t Br0 = (size_t)(n0 + arow0) * K3 + aseg;
    size_t Br1 = (size_t)(n0 + arow1) * K3 + aseg;

    float acc[4][4][4];
#pragma unroll
    for (int i = 0; i < 4; i++)
#pragma unroll
        for (int j = 0; j < 4; j++)
#pragma unroll
            for (int q = 0; q < 4; q++) acc[i][j][q] = 0.0f;

    // prologue: chunk 0 -> stage 0
    {
        uint4 a0 = *(const uint4*)(Acat + Ar0);
        uint4 a1 = *(const uint4*)(Acat + Ar1);
        uint4 b0 = *(const uint4*)(Bexp + Br0);
        uint4 b1 = *(const uint4*)(Bexp + Br1);
        *(uint4*)&As[0][arow0][aseg] = a0;
        *(uint4*)&As[0][arow1][aseg] = a1;
        *(uint4*)&Bs[0][arow0][aseg] = b0;
        *(uint4*)&Bs[0][arow1][aseg] = b1;
    }
    __syncthreads();

    uint4 pa0, pa1, pb0, pb1;
#pragma unroll 1
    for (int c = 0; c < NCH; c++) {
        int s = c & 1;
        bool pf = (c + 1 < NCH);
        if (pf) {
            size_t kb = (size_t)(c + 1) * BK;
            pa0 = *(const uint4*)(Acat + Ar0 + kb);
            pa1 = *(const uint4*)(Acat + Ar1 + kb);
            pb0 = *(const uint4*)(Bexp + Br0 + kb);
            pb1 = *(const uint4*)(Bexp + Br1 + kb);
        }
#pragma unroll
        for (int ks = 0; ks < 2; ks++) {
            int kc = ks * 16;
            uint32_t af[4][4], bfr[4][2];
#pragma unroll
            for (int mt = 0; mt < 4; mt++) {
                int r = wm * 64 + mt * 16 + g;
                af[mt][0] = *(const uint32_t*)&As[s][r    ][kc + tig * 2];
                af[mt][1] = *(const uint32_t*)&As[s][r + 8][kc + tig * 2];
                af[mt][2] = *(const uint32_t*)&As[s][r    ][kc + tig * 2 + 8];
                af[mt][3] = *(const uint32_t*)&As[s][r + 8][kc + tig * 2 + 8];
            }
#pragma unroll
            for (int nt = 0; nt < 4; nt++) {
                int rb = wn * 32 + nt * 8 + g;
                bfr[nt][0] = *(const uint32_t*)&Bs[s][rb][kc + tig * 2];
                bfr[nt][1] = *(const uint32_t*)&Bs[s][rb][kc + tig * 2 + 8];
            }
#pragma unroll
            for (int mt = 0; mt < 4; mt++)
#pragma unroll
                for (int nt = 0; nt < 4; nt++)
                    mma16816(acc[mt][nt], af[mt], bfr[nt]);
        }
        if (pf) {
            int d = s ^ 1;
            *(uint4*)&As[d][arow0][aseg] = pa0;
            *(uint4*)&As[d][arow1][aseg] = pa1;
            *(uint4*)&Bs[d][arow0][aseg] = pb0;
            *(uint4*)&Bs[d][arow1][aseg] = pb1;
        }
        __syncthreads();
    }

    // ---------------- epilogue ----------------
#pragma unroll
    for (int mt = 0; mt < 4; mt++) {
#pragma unroll
        for (int half = 0; half < 2; half++) {
            int ml = wm * 64 + mt * 16 + g + half * 8;   // local row 0..127
            int m = m0 + ml;
            if (m >= cnt) continue;
            if (MODE == 0) {
                int slot = base + m;
                float wt = wt_s[ml];
                __nv_bfloat16* dst = g_acat + (size_t)slot * K3;
#pragma unroll
                for (int nt = 0; nt < 4; nt++) {
                    int n = n0 + wn * 32 + nt * 8 + tig * 2;
                    float h0 = acc[mt][nt][half * 2 + 0];
                    float h1 = acc[mt][nt][half * 2 + 1];
                    float a0 = (h0 > 0.0f) ? wt * h0 * h0 : 0.0f;
                    float a1 = (h1 > 0.0f) ? wt * h1 * h1 : 0.0f;
                    __nv_bfloat16 hi0 = __float2bfloat16(a0);
                    __nv_bfloat16 hi1 = __float2bfloat16(a1);
                    __nv_bfloat16 lo0 = __float2bfloat16(a0 - __bfloat162float(hi0));
                    __nv_bfloat16 lo1 = __float2bfloat16(a1 - __bfloat162float(hi1));
                    __nv_bfloat162 hh; hh.x = hi0; hh.y = hi1;
                    __nv_bfloat162 ll; ll.x = lo0; ll.y = lo1;
                    *(__nv_bfloat162*)(dst + n)        = hh;
                    *(__nv_bfloat162*)(dst + 1024 + n) = hh;
                    *(__nv_bfloat162*)(dst + 2048 + n) = ll;
                }
            } else {
                int tok = tok_s[ml];
                float* orow = out + (size_t)tok * D_DIM;
#pragma unroll
                for (int nt = 0; nt < 4; nt++) {
                    int n = n0 + wn * 32 + nt * 8 + tig * 2;
                    atomicAdd(&orow[n],     acc[mt][nt][half * 2 + 0]);
                    atomicAdd(&orow[n + 1], acc[mt][nt][half * 2 + 1]);
                }
            }
        }
    }
}

// ---------------- launch ------------------------------------------------------
extern "C" void kernel_launch(void* const* d_in, const int* in_sizes, int n_in,
                              void* d_out, int out_size) {
    const float* x  = (const float*)d_in[0];   // [2,2048,1024]
    const float* rw = (const float*)d_in[1];   // [8,1024]
    const float* w1 = (const float*)d_in[2];   // [1024, 8192]
    const float* w2 = (const float*)d_in[3];   // [8192, 1024]
    float* out = (float*)d_out;

    zero_kernel<<<(T_TOK * D_DIM + 255) / 256, 256>>>(out);
    convert_x<<<(T_TOK * D_DIM + 255) / 256, 256>>>(x);

    dim3 tg(32, 32, E_NUM), tb(32, 8);
    convert_w<<<tg, tb>>>(w1, 0);
    convert_w<<<tg, tb>>>(w2, 1);

    router_kernel<<<(T_TOK * 32 + 255) / 256, 256>>>(x, rw);
    offsets_kernel<<<1, 32>>>();
    fill_kernel<<<(T_TOK + 255) / 256, 256>>>();

    dim3 gup(W_DIM / 128, T_TOK / 128, E_NUM);   // (8, 32, 8)
    moe_gemm<0><<<gup, 256>>>(out);
    dim3 gdn(D_DIM / 128, T_TOK / 128, E_NUM);   // (8, 32, 8)
    moe_gemm<1><<<gdn, 256>>>(out);
}

// round 9
// speedup vs baseline: 1.4343x; 1.4343x over previous
#include <cuda_runtime.h>
#include <cuda_bf16.h>
#include <math.h>
#include <stdint.h>

// ---------------- problem constants ----------------------------------------
#define T_TOK 4096
#define D_DIM 1024
#define E_NUM 8
#define W_DIM 1024
#define SLOTS 8192          // T*2 (top-2)
#define K3    3072          // concatenated K: A=[hi|hi|lo], B=[hi|lo|hi]
#define BK    64
#define NCH   (K3 / BK)     // 48
#define SAS   72            // smem row stride (bf16): 64 + 8 pad -> conflict-free

// dynamic smem layout (elements/bytes)
#define STAGE_BYTES (128 * SAS * 2)          // 18432 per operand per stage
#define A_OFF(s)  ((s) * STAGE_BYTES)        // 0, 18432
#define B_OFF(s)  (2 * STAGE_BYTES + (s) * STAGE_BYTES)  // 36864, 55296
#define TOK_OFF   (4 * STAGE_BYTES)          // 73728
#define WT_OFF    (TOK_OFF + 512)
#define SM_BYTES  (TOK_OFF + 1024)           // 74752

// ---------------- device scratch --------------------------------------------
__device__ int   g_count[E_NUM];
__device__ int   g_fill [E_NUM];
__device__ int   g_off  [E_NUM + 1];
__device__ int   g_sel  [T_TOK * 2];
__device__ float g_selw [T_TOK * 2];
__device__ int   g_tok  [SLOTS];
__device__ float g_wt   [SLOTS];
__device__ __nv_bfloat16 g_xcat [(size_t)T_TOK * K3];          // 25 MB
__device__ __nv_bfloat16 g_w1cat[(size_t)E_NUM * W_DIM * K3];  // 50 MB [e][n][k]
__device__ __nv_bfloat16 g_w2cat[(size_t)E_NUM * D_DIM * K3];  // 50 MB [e][d][k]
__device__ __nv_bfloat16 g_acat [(size_t)SLOTS * K3];          // 50 MB [slot][k]

// ---------------- small kernels ---------------------------------------------
__global__ void zero_kernel(float* __restrict__ out) {
    int i = blockIdx.x * blockDim.x + threadIdx.x;
    if (i < T_TOK * D_DIM) out[i] = 0.0f;
    if (i < E_NUM) { g_count[i] = 0; g_fill[i] = 0; }
}

__global__ void router_kernel(const float* __restrict__ x, const float* __restrict__ rw) {
    int warp = (blockIdx.x * blockDim.x + threadIdx.x) >> 5;
    int lane = threadIdx.x & 31;
    if (warp >= T_TOK) return;
    const float* xr = x + (size_t)warp * D_DIM;
    float p[E_NUM];
#pragma unroll
    for (int e = 0; e < E_NUM; e++) p[e] = 0.0f;
    for (int d = lane; d < D_DIM; d += 32) {
        float xv = xr[d];
#pragma unroll
        for (int e = 0; e < E_NUM; e++) p[e] += xv * rw[e * D_DIM + d];
    }
#pragma unroll
    for (int e = 0; e < E_NUM; e++)
#pragma unroll
        for (int o = 16; o; o >>= 1) p[e] += __shfl_xor_sync(0xffffffffu, p[e], o);
    if (lane == 0) {
        int i1 = 0; float v1 = p[0];
#pragma unroll
        for (int e = 1; e < E_NUM; e++) if (p[e] > v1) { v1 = p[e]; i1 = e; }
        int i2 = -1; float v2 = -3.0e38f;
#pragma unroll
        for (int e = 0; e < E_NUM; e++) if (e != i1 && p[e] > v2) { v2 = p[e]; i2 = e; }
        float p1 = 1.0f / (1.0f + expf(-v1));
        float p2 = 1.0f / (1.0f + expf(-v2));
        float s = p1 + p2 + 1e-20f;
        g_sel [warp * 2 + 0] = i1;  g_sel [warp * 2 + 1] = i2;
        g_selw[warp * 2 + 0] = p1 / s;
        g_selw[warp * 2 + 1] = p2 / s;
        atomicAdd(&g_count[i1], 1);
        atomicAdd(&g_count[i2], 1);
    }
}

__global__ void offsets_kernel() {
    if (threadIdx.x == 0 && blockIdx.x == 0) {
        int s = 0;
#pragma unroll
        for (int e = 0; e < E_NUM; e++) { g_off[e] = s; s += g_count[e]; }
        g_off[E_NUM] = s;
    }
}

__global__ void fill_kernel() {
    int t = blockIdx.x * blockDim.x + threadIdx.x;
    if (t >= T_TOK) return;
#pragma unroll
    for (int k = 0; k < 2; k++) {
        int e = g_sel[t * 2 + k];
        int pos = g_off[e] + atomicAdd(&g_fill[e], 1);
        g_tok[pos] = t;
        g_wt [pos] = g_selw[t * 2 + k];
    }
}

// x -> [hi | hi | lo] bf16, row-major [T][3072]
__global__ void convert_x(const float* __restrict__ x) {
    int i = blockIdx.x * blockDim.x + threadIdx.x;
    if (i >= T_TOK * D_DIM) return;
    int t = i >> 10, d = i & 1023;
    float v = x[i];
    __nv_bfloat16 hi = __float2bfloat16(v);
    __nv_bfloat16 lo = __float2bfloat16(v - __bfloat162float(hi));
    size_t b = (size_t)t * K3;
    g_xcat[b + d] = hi; g_xcat[b + 1024 + d] = hi; g_xcat[b + 2048 + d] = lo;
}

// Per-expert 1024x1024 transpose + split: dst[e][n][k-seg], segs [hi|lo|hi]
__global__ void convert_w(const float* __restrict__ src, int sel) {
    __shared__ float tile[32][33];
    int e = blockIdx.z;
    int r0 = blockIdx.y * 32, c0 = blockIdx.x * 32;
    int src_ld  = sel ? 1024 : 8192;
    int row_off = sel ? e * 1024 : 0;
    int col_off = sel ? 0 : e * 1024;
    const float* s = src + (size_t)(row_off + r0) * src_ld + col_off + c0;
#pragma unroll
    for (int i = threadIdx.y; i < 32; i += 8)
        tile[i][threadIdx.x] = s[(size_t)i * src_ld + threadIdx.x];
    __syncthreads();
    __nv_bfloat16* d = (sel ? g_w2cat : g_w1cat) + (size_t)e * 1024 * K3;
#pragma unroll
    for (int i = threadIdx.y; i < 32; i += 8) {
        int c = c0 + i;               // dst row (N index)
        int r = r0 + threadIdx.x;     // dst col (K index)
        float v = tile[threadIdx.x][i];
        __nv_bfloat16 hi = __float2bfloat16(v);
        __nv_bfloat16 lo = __float2bfloat16(v - __bfloat162float(hi));
        size_t bi = (size_t)c * K3 + r;
        d[bi] = hi; d[bi + 1024] = lo; d[bi + 2048] = hi;
    }
}

// ---------------- mma.sync helper -------------------------------------------
__device__ __forceinline__ void mma16816(float* d, const uint32_t* a, const uint32_t* b) {
    asm volatile(
        "mma.sync.aligned.m16n8k16.row.col.f32.bf16.bf16.f32 "
        "{%0,%1,%2,%3}, {%4,%5,%6,%7}, {%8,%9}, {%0,%1,%2,%3};"
        : "+f"(d[0]), "+f"(d[1]), "+f"(d[2]), "+f"(d[3])
        : "r"(a[0]), "r"(a[1]), "r"(a[2]), "r"(a[3]), "r"(b[0]), "r"(b[1]));
}

// ---------------- grouped GEMM (HMMA via mma.sync, bf16x3, BK=64) -----------
// MODE 0: up-proj  (A = g_xcat gathered by token, B = g_w1cat, epi -> g_acat split)
// MODE 1: down-proj(A = g_acat by slot,          B = g_w2cat, epi -> atomicAdd out)
template <int MODE>
__global__ void __launch_bounds__(256) moe_gemm(float* __restrict__ out) {
    extern __shared__ char sm[];
    __nv_bfloat16* Asm = (__nv_bfloat16*)sm;           // [2][128][SAS] via A_OFF
    __nv_bfloat16* Bsm = (__nv_bfloat16*)(sm);         // offsets below
    int*   tok_s = (int*)  (sm + TOK_OFF);
    float* wt_s  = (float*)(sm + WT_OFF);
    (void)Asm; (void)Bsm;

    int e = blockIdx.z;
    int cnt = g_count[e];
    int m0 = blockIdx.y * 128;
    if (m0 >= cnt) return;
    int base = g_off[e];
    int n0 = blockIdx.x * 128;

    int tid = threadIdx.x, lane = tid & 31, wid = tid >> 5;
    int wm = wid & 1, wn = wid >> 1;        // warp grid 2 x 4 -> 64 x 32 per warp
    int g = lane >> 2, tig = lane & 3;

    if (tid < 128) {
        int slot = base + m0 + tid; if (slot >= SLOTS) slot = SLOTS - 1;
        tok_s[tid] = g_tok[slot];
        wt_s [tid] = g_wt[slot];
    }
    __syncthreads();

    const __nv_bfloat16* Acat = MODE ? g_acat : g_xcat;
    const __nv_bfloat16* Bexp = (MODE ? g_w2cat : g_w1cat) + (size_t)e * 1024 * K3;

    // global load assignment per chunk: A tile 128x64 = 1024 uint4, 4/thread
    // rows arow0, arow1 ; col segs aseg, aseg+32
    int arow0 = tid >> 2, arow1 = arow0 + 64;
    int aseg  = (tid & 3) * 8;
    size_t Ar0, Ar1;
    if (MODE == 0) {
        Ar0 = (size_t)tok_s[arow0] * K3 + aseg;
        Ar1 = (size_t)tok_s[arow1] * K3 + aseg;
    } else {
        int s0 = base + m0 + arow0; if (s0 >= SLOTS) s0 = SLOTS - 1;
        int s1 = base + m0 + arow1; if (s1 >= SLOTS) s1 = SLOTS - 1;
        Ar0 = (size_t)s0 * K3 + aseg;
        Ar1 = (size_t)s1 * K3 + aseg;
    }
    size_t Br0 = (size_t)(n0 + arow0) * K3 + aseg;
    size_t Br1 = (size_t)(n0 + arow1) * K3 + aseg;

    float acc[4][4][4];
#pragma unroll
    for (int i = 0; i < 4; i++)
#pragma unroll
        for (int j = 0; j < 4; j++)
#pragma unroll
            for (int q = 0; q < 4; q++) acc[i][j][q] = 0.0f;

#define AS(s, r, c) (*(__nv_bfloat16*)(sm + A_OFF(s) + ((r) * SAS + (c)) * 2))
#define BS(s, r, c) (*(__nv_bfloat16*)(sm + B_OFF(s) + ((r) * SAS + (c)) * 2))

    // prologue: chunk 0 -> stage 0
    {
        uint4 a00 = *(const uint4*)(Acat + Ar0);
        uint4 a01 = *(const uint4*)(Acat + Ar0 + 32);
        uint4 a10 = *(const uint4*)(Acat + Ar1);
        uint4 a11 = *(const uint4*)(Acat + Ar1 + 32);
        uint4 b00 = *(const uint4*)(Bexp + Br0);
        uint4 b01 = *(const uint4*)(Bexp + Br0 + 32);
        uint4 b10 = *(const uint4*)(Bexp + Br1);
        uint4 b11 = *(const uint4*)(Bexp + Br1 + 32);
        *(uint4*)&AS(0, arow0, aseg)      = a00;
        *(uint4*)&AS(0, arow0, aseg + 32) = a01;
        *(uint4*)&AS(0, arow1, aseg)      = a10;
        *(uint4*)&AS(0, arow1, aseg + 32) = a11;
        *(uint4*)&BS(0, arow0, aseg)      = b00;
        *(uint4*)&BS(0, arow0, aseg + 32) = b01;
        *(uint4*)&BS(0, arow1, aseg)      = b10;
        *(uint4*)&BS(0, arow1, aseg + 32) = b11;
    }
    __syncthreads();

    uint4 pa00, pa01, pa10, pa11, pb00, pb01, pb10, pb11;
#pragma unroll 1
    for (int c = 0; c < NCH; c++) {
        int s = c & 1;
        bool pf = (c + 1 < NCH);
        if (pf) {
            size_t kb = (size_t)(c + 1) * BK;
            pa00 = *(const uint4*)(Acat + Ar0 + kb);
            pa01 = *(const uint4*)(Acat + Ar0 + kb + 32);
            pa10 = *(const uint4*)(Acat + Ar1 + kb);
            pa11 = *(const uint4*)(Acat + Ar1 + kb + 32);
            pb00 = *(const uint4*)(Bexp + Br0 + kb);
            pb01 = *(const uint4*)(Bexp + Br0 + kb + 32);
            pb10 = *(const uint4*)(Bexp + Br1 + kb);
            pb11 = *(const uint4*)(Bexp + Br1 + kb + 32);
        }
#pragma unroll
        for (int ks = 0; ks < 4; ks++) {
            int kc = ks * 16;
            uint32_t af[4][4], bfr[4][2];
#pragma unroll
            for (int mt = 0; mt < 4; mt++) {
                int r = wm * 64 + mt * 16 + g;
                af[mt][0] = *(const uint32_t*)&AS(s, r,     kc + tig * 2);
                af[mt][1] = *(const uint32_t*)&AS(s, r + 8, kc + tig * 2);
                af[mt][2] = *(const uint32_t*)&AS(s, r,     kc + tig * 2 + 8);
                af[mt][3] = *(const uint32_t*)&AS(s, r + 8, kc + tig * 2 + 8);
            }
#pragma unroll
            for (int nt = 0; nt < 4; nt++) {
                int rb = wn * 32 + nt * 8 + g;
                bfr[nt][0] = *(const uint32_t*)&BS(s, rb, kc + tig * 2);
                bfr[nt][1] = *(const uint32_t*)&BS(s, rb, kc + tig * 2 + 8);
            }
#pragma unroll
            for (int mt = 0; mt < 4; mt++)
#pragma unroll
                for (int nt = 0; nt < 4; nt++)
                    mma16816(acc[mt][nt], af[mt], bfr[nt]);
        }
        if (pf) {
            int d = s ^ 1;
            *(uint4*)&AS(d, arow0, aseg)      = pa00;
            *(uint4*)&AS(d, arow0, aseg + 32) = pa01;
            *(uint4*)&AS(d, arow1, aseg)      = pa10;
            *(uint4*)&AS(d, arow1, aseg + 32) = pa11;
            *(uint4*)&BS(d, arow0, aseg)      = pb00;
            *(uint4*)&BS(d, arow0, aseg + 32) = pb01;
            *(uint4*)&BS(d, arow1, aseg)      = pb10;
            *(uint4*)&BS(d, arow1, aseg + 32) = pb11;
        }
        __syncthreads();
    }
#undef AS
#undef BS

    // ---------------- epilogue ----------------
#pragma unroll
    for (int mt = 0; mt < 4; mt++) {
#pragma unroll
        for (int half = 0; half < 2; half++) {
            int ml = wm * 64 + mt * 16 + g + half * 8;   // local row 0..127
            int m = m0 + ml;
            if (m >= cnt) continue;
            if (MODE == 0) {
                int slot = base + m;
                float wt = wt_s[ml];
                __nv_bfloat16* dst = g_acat + (size_t)slot * K3;
#pragma unroll
                for (int nt = 0; nt < 4; nt++) {
                    int n = n0 + wn * 32 + nt * 8 + tig * 2;
                    float h0 = acc[mt][nt][half * 2 + 0];
                    float h1 = acc[mt][nt][half * 2 + 1];
                    float a0 = (h0 > 0.0f) ? wt * h0 * h0 : 0.0f;
                    float a1 = (h1 > 0.0f) ? wt * h1 * h1 : 0.0f;
                    __nv_bfloat16 hi0 = __float2bfloat16(a0);
                    __nv_bfloat16 hi1 = __float2bfloat16(a1);
                    __nv_bfloat16 lo0 = __float2bfloat16(a0 - __bfloat162float(hi0));
                    __nv_bfloat16 lo1 = __float2bfloat16(a1 - __bfloat162float(hi1));
                    __nv_bfloat162 hh; hh.x = hi0; hh.y = hi1;
                    __nv_bfloat162 ll; ll.x = lo0; ll.y = lo1;
                    *(__nv_bfloat162*)(dst + n)        = hh;
                    *(__nv_bfloat162*)(dst + 1024 + n) = hh;
                    *(__nv_bfloat162*)(dst + 2048 + n) = ll;
                }
            } else {
                int tok = tok_s[ml];
                float* orow = out + (size_t)tok * D_DIM;
#pragma unroll
                for (int nt = 0; nt < 4; nt++) {
                    int n = n0 + wn * 32 + nt * 8 + tig * 2;
                    atomicAdd(&orow[n],     acc[mt][nt][half * 2 + 0]);
                    atomicAdd(&orow[n + 1], acc[mt][nt][half * 2 + 1]);
                }
            }
        }
    }
}

// ---------------- launch ------------------------------------------------------
extern "C" void kernel_launch(void* const* d_in, const int* in_sizes, int n_in,
                              void* d_out, int out_size) {
    const float* x  = (const float*)d_in[0];   // [2,2048,1024]
    const float* rw = (const float*)d_in[1];   // [8,1024]
    const float* w1 = (const float*)d_in[2];   // [1024, 8192]
    const float* w2 = (const float*)d_in[3];   // [8192, 1024]
    float* out = (float*)d_out;

    zero_kernel<<<(T_TOK * D_DIM + 255) / 256, 256>>>(out);
    convert_x<<<(T_TOK * D_DIM + 255) / 256, 256>>>(x);

    dim3 tg(32, 32, E_NUM), tb(32, 8);
    convert_w<<<tg, tb>>>(w1, 0);
    convert_w<<<tg, tb>>>(w2, 1);

    router_kernel<<<(T_TOK * 32 + 255) / 256, 256>>>(x, rw);
    offsets_kernel<<<1, 32>>>();
    fill_kernel<<<(T_TOK + 255) / 256, 256>>>();

    cudaFuncSetAttribute(moe_gemm<0>, cudaFuncAttributeMaxDynamicSharedMemorySize, SM_BYTES);
    cudaFuncSetAttribute(moe_gemm<1>, cudaFuncAttributeMaxDynamicSharedMemorySize, SM_BYTES);

    dim3 gup(W_DIM / 128, T_TOK / 128, E_NUM);   // (8, 32, 8)
    moe_gemm<0><<<gup, 256, SM_BYTES>>>(out);
    dim3 gdn(D_DIM / 128, T_TOK / 128, E_NUM);   // (8, 32, 8)
    moe_gemm<1><<<gdn, 256, SM_BYTES>>>(out);
}

// round 10
// speedup vs baseline: 1.5849x; 1.1050x over previous
#include <cuda_runtime.h>
#include <cuda_bf16.h>
#include <math.h>
#include <stdint.h>

// ---------------- problem constants ----------------------------------------
#define T_TOK 4096
#define D_DIM 1024
#define E_NUM 8
#define W_DIM 1024
#define SLOTS 8192          // T*2 (top-2)
#define K3    3072          // concatenated K: A=[hi|hi|lo], B=[hi|lo|hi]
#define BK    32
#define NCH   (K3 / BK)     // 96
#define SAS   40            // smem row stride (bf16) -> conflict-free frag LDS

// ---------------- device scratch --------------------------------------------
__device__ int   g_count[E_NUM];
__device__ int   g_fill [E_NUM];
__device__ int   g_off  [E_NUM + 1];
__device__ int   g_sel  [T_TOK * 2];
__device__ float g_selw [T_TOK * 2];
__device__ int   g_tok  [SLOTS];
__device__ float g_wt   [SLOTS];
__device__ __nv_bfloat16 g_xcat [(size_t)T_TOK * K3];          // 25 MB
__device__ __nv_bfloat16 g_w1cat[(size_t)E_NUM * W_DIM * K3];  // 50 MB [e][n][k]
__device__ __nv_bfloat16 g_w2cat[(size_t)E_NUM * D_DIM * K3];  // 50 MB [e][d][k]
__device__ __nv_bfloat16 g_acat [(size_t)SLOTS * K3];          // 50 MB [slot][k]

// ---------------- small kernels ---------------------------------------------
__global__ void zero_kernel(float* __restrict__ out) {
    int i = blockIdx.x * blockDim.x + threadIdx.x;
    if (i < T_TOK * D_DIM) out[i] = 0.0f;
    if (i < E_NUM) { g_count[i] = 0; g_fill[i] = 0; }
}

__global__ void router_kernel(const float* __restrict__ x, const float* __restrict__ rw) {
    int warp = (blockIdx.x * blockDim.x + threadIdx.x) >> 5;
    int lane = threadIdx.x & 31;
    if (warp >= T_TOK) return;
    const float* xr = x + (size_t)warp * D_DIM;
    float p[E_NUM];
#pragma unroll
    for (int e = 0; e < E_NUM; e++) p[e] = 0.0f;
    for (int d = lane; d < D_DIM; d += 32) {
        float xv = xr[d];
#pragma unroll
        for (int e = 0; e < E_NUM; e++) p[e] += xv * rw[e * D_DIM + d];
    }
#pragma unroll
    for (int e = 0; e < E_NUM; e++)
#pragma unroll
        for (int o = 16; o; o >>= 1) p[e] += __shfl_xor_sync(0xffffffffu, p[e], o);
    if (lane == 0) {
        int i1 = 0; float v1 = p[0];
#pragma unroll
        for (int e = 1; e < E_NUM; e++) if (p[e] > v1) { v1 = p[e]; i1 = e; }
        int i2 = -1; float v2 = -3.0e38f;
#pragma unroll
        for (int e = 0; e < E_NUM; e++) if (e != i1 && p[e] > v2) { v2 = p[e]; i2 = e; }
        float p1 = 1.0f / (1.0f + expf(-v1));
        float p2 = 1.0f / (1.0f + expf(-v2));
        float s = p1 + p2 + 1e-20f;
        g_sel [warp * 2 + 0] = i1;  g_sel [warp * 2 + 1] = i2;
        g_selw[warp * 2 + 0] = p1 / s;
        g_selw[warp * 2 + 1] = p2 / s;
        atomicAdd(&g_count[i1], 1);
        atomicAdd(&g_count[i2], 1);
    }
}

__global__ void offsets_kernel() {
    if (threadIdx.x == 0 && blockIdx.x == 0) {
        int s = 0;
#pragma unroll
        for (int e = 0; e < E_NUM; e++) { g_off[e] = s; s += g_count[e]; }
        g_off[E_NUM] = s;
    }
}

__global__ void fill_kernel() {
    int t = blockIdx.x * blockDim.x + threadIdx.x;
    if (t >= T_TOK) return;
#pragma unroll
    for (int k = 0; k < 2; k++) {
        int e = g_sel[t * 2 + k];
        int pos = g_off[e] + atomicAdd(&g_fill[e], 1);
        g_tok[pos] = t;
        g_wt [pos] = g_selw[t * 2 + k];
    }
}

// x -> [hi | hi | lo] bf16, row-major [T][3072]
__global__ void convert_x(const float* __restrict__ x) {
    int i = blockIdx.x * blockDim.x + threadIdx.x;
    if (i >= T_TOK * D_DIM) return;
    int t = i >> 10, d = i & 1023;
    float v = x[i];
    __nv_bfloat16 hi = __float2bfloat16(v);
    __nv_bfloat16 lo = __float2bfloat16(v - __bfloat162float(hi));
    size_t b = (size_t)t * K3;
    g_xcat[b + d] = hi; g_xcat[b + 1024 + d] = hi; g_xcat[b + 2048 + d] = lo;
}

// Per-expert 1024x1024 transpose + split: dst[e][n][k-seg], segs [hi|lo|hi]
__global__ void convert_w(const float* __restrict__ src, int sel) {
    __shared__ float tile[32][33];
    int e = blockIdx.z;
    int r0 = blockIdx.y * 32, c0 = blockIdx.x * 32;
    int src_ld  = sel ? 1024 : 8192;
    int row_off = sel ? e * 1024 : 0;
    int col_off = sel ? 0 : e * 1024;
    const float* s = src + (size_t)(row_off + r0) * src_ld + col_off + c0;
#pragma unroll
    for (int i = threadIdx.y; i < 32; i += 8)
        tile[i][threadIdx.x] = s[(size_t)i * src_ld + threadIdx.x];
    __syncthreads();
    __nv_bfloat16* d = (sel ? g_w2cat : g_w1cat) + (size_t)e * 1024 * K3;
#pragma unroll
    for (int i = threadIdx.y; i < 32; i += 8) {
        int c = c0 + i;               // dst row (N index)
        int r = r0 + threadIdx.x;     // dst col (K index)
        float v = tile[threadIdx.x][i];
        __nv_bfloat16 hi = __float2bfloat16(v);
        __nv_bfloat16 lo = __float2bfloat16(v - __bfloat162float(hi));
        size_t bi = (size_t)c * K3 + r;
        d[bi] = hi; d[bi + 1024] = lo; d[bi + 2048] = hi;
    }
}

// ---------------- mma.sync helper -------------------------------------------
__device__ __forceinline__ void mma16816(float* d, const uint32_t* a, const uint32_t* b) {
    asm volatile(
        "mma.sync.aligned.m16n8k16.row.col.f32.bf16.bf16.f32 "
        "{%0,%1,%2,%3}, {%4,%5,%6,%7}, {%8,%9}, {%0,%1,%2,%3};"
        : "+f"(d[0]), "+f"(d[1]), "+f"(d[2]), "+f"(d[3])
        : "r"(a[0]), "r"(a[1]), "r"(a[2]), "r"(a[3]), "r"(b[0]), "r"(b[1]));
}

// ---------------- grouped GEMM (HMMA via mma.sync, bf16x3, 2 CTA/SM) --------
// MODE 0: up-proj  (A = g_xcat gathered by token, B = g_w1cat, epi -> g_acat split)
// MODE 1: down-proj(A = g_acat by slot,          B = g_w2cat, epi -> atomicAdd out)
template <int MODE>
__global__ void __launch_bounds__(256, 2) moe_gemm(float* __restrict__ out) {
    __shared__ __nv_bfloat16 As[2][128][SAS];
    __shared__ __nv_bfloat16 Bs[2][128][SAS];
    __shared__ int   tok_s[128];
    __shared__ float wt_s [128];

    int e = blockIdx.z;
    int cnt = g_count[e];
    int m0 = blockIdx.y * 128;
    if (m0 >= cnt) return;
    int base = g_off[e];
    int n0 = blockIdx.x * 128;

    int tid = threadIdx.x, lane = tid & 31, wid = tid >> 5;
    int wm = wid & 1, wn = wid >> 1;        // warp grid 2 x 4 -> 64 x 32 per warp
    int g = lane >> 2, tig = lane & 3;

    if (tid < 128) {
        int slot = base + m0 + tid; if (slot >= SLOTS) slot = SLOTS - 1;
        tok_s[tid] = g_tok[slot];
        wt_s [tid] = g_wt[slot];
    }
    __syncthreads();

    // global load assignment: 512 uint4 per tile, 2 per thread (rows r, r+64)
    int arow0 = tid >> 2, arow1 = arow0 + 64;
    int aseg  = (tid & 3) * 8;
    const __nv_bfloat16 *Ab0, *Ab1;
    if (MODE == 0) {
        Ab0 = g_xcat + (size_t)tok_s[arow0] * K3 + aseg;
        Ab1 = g_xcat + (size_t)tok_s[arow1] * K3 + aseg;
    } else {
        int s0 = base + m0 + arow0; if (s0 >= SLOTS) s0 = SLOTS - 1;
        int s1 = base + m0 + arow1; if (s1 >= SLOTS) s1 = SLOTS - 1;
        Ab0 = g_acat + (size_t)s0 * K3 + aseg;
        Ab1 = g_acat + (size_t)s1 * K3 + aseg;
    }
    const __nv_bfloat16* Bexp = (MODE ? g_w2cat : g_w1cat) + (size_t)e * 1024 * K3;
    const __nv_bfloat16* Bb0 = Bexp + (size_t)(n0 + arow0) * K3 + aseg;
    const __nv_bfloat16* Bb1 = Bexp + (size_t)(n0 + arow1) * K3 + aseg;

    float acc[4][4][4];
#pragma unroll
    for (int i = 0; i < 4; i++)
#pragma unroll
        for (int j = 0; j < 4; j++)
#pragma unroll
            for (int q = 0; q < 4; q++) acc[i][j][q] = 0.0f;

    // prologue: chunk 0 -> stage 0
    {
        uint4 a0 = *(const uint4*)(Ab0);
        uint4 a1 = *(const uint4*)(Ab1);
        uint4 b0 = *(const uint4*)(Bb0);
        uint4 b1 = *(const uint4*)(Bb1);
        *(uint4*)&As[0][arow0][aseg] = a0;
        *(uint4*)&As[0][arow1][aseg] = a1;
        *(uint4*)&Bs[0][arow0][aseg] = b0;
        *(uint4*)&Bs[0][arow1][aseg] = b1;
    }
    __syncthreads();

#pragma unroll 1
    for (int c = 0; c < NCH; c++) {
        int s = c & 1;
        int d = s ^ 1;
        bool pf = (c + 1 < NCH);
        int kn = (c + 1) * BK;

        // ---- phase A-prefetch (8 regs live) ----
        uint4 pa0, pa1;
        if (pf) {
            pa0 = *(const uint4*)(Ab0 + kn);
            pa1 = *(const uint4*)(Ab1 + kn);
        }
        // ---- ks = 0: frags + MMA ----
        {
            const int kc = 0;
            uint32_t bfr[4][2];
#pragma unroll
            for (int nt = 0; nt < 4; nt++) {
                int rb = wn * 32 + nt * 8 + g;
                bfr[nt][0] = *(const uint32_t*)&Bs[s][rb][kc + tig * 2];
                bfr[nt][1] = *(const uint32_t*)&Bs[s][rb][kc + tig * 2 + 8];
            }
#pragma unroll
            for (int mt = 0; mt < 4; mt++) {
                uint32_t af[4];
                int r = wm * 64 + mt * 16 + g;
                af[0] = *(const uint32_t*)&As[s][r    ][kc + tig * 2];
                af[1] = *(const uint32_t*)&As[s][r + 8][kc + tig * 2];
                af[2] = *(const uint32_t*)&As[s][r    ][kc + tig * 2 + 8];
                af[3] = *(const uint32_t*)&As[s][r + 8][kc + tig * 2 + 8];
#pragma unroll
                for (int nt = 0; nt < 4; nt++)
                    mma16816(acc[mt][nt], af, bfr[nt]);
            }
        }
        // ---- store A-prefetch, fetch B-prefetch ----
        uint4 pb0, pb1;
        if (pf) {
            *(uint4*)&As[d][arow0][aseg] = pa0;
            *(uint4*)&As[d][arow1][aseg] = pa1;
            pb0 = *(const uint4*)(Bb0 + kn);
            pb1 = *(const uint4*)(Bb1 + kn);
        }
        // ---- ks = 1: frags + MMA ----
        {
            const int kc = 16;
            uint32_t bfr[4][2];
#pragma unroll
            for (int nt = 0; nt < 4; nt++) {
                int rb = wn * 32 + nt * 8 + g;
                bfr[nt][0] = *(const uint32_t*)&Bs[s][rb][kc + tig * 2];
                bfr[nt][1] = *(const uint32_t*)&Bs[s][rb][kc + tig * 2 + 8];
            }
#pragma unroll
            for (int mt = 0; mt < 4; mt++) {
                uint32_t af[4];
                int r = wm * 64 + mt * 16 + g;
                af[0] = *(const uint32_t*)&As[s][r    ][kc + tig * 2];
                af[1] = *(const uint32_t*)&As[s][r + 8][kc + tig * 2];
                af[2] = *(const uint32_t*)&As[s][r    ][kc + tig * 2 + 8];
                af[3] = *(const uint32_t*)&As[s][r + 8][kc + tig * 2 + 8];
#pragma unroll
                for (int nt = 0; nt < 4; nt++)
                    mma16816(acc[mt][nt], af, bfr[nt]);
            }
        }
        // ---- store B-prefetch ----
        if (pf) {
            *(uint4*)&Bs[d][arow0][aseg] = pb0;
            *(uint4*)&Bs[d][arow1][aseg] = pb1;
        }
        __syncthreads();
    }

    // ---------------- epilogue ----------------
#pragma unroll
    for (int mt = 0; mt < 4; mt++) {
#pragma unroll
        for (int half = 0; half < 2; half++) {
            int ml = wm * 64 + mt * 16 + g + half * 8;   // local row 0..127
            int m = m0 + ml;
            if (m >= cnt) continue;
            if (MODE == 0) {
                int slot = base + m;
                float wt = wt_s[ml];
                __nv_bfloat16* dst = g_acat + (size_t)slot * K3;
#pragma unroll
                for (int nt = 0; nt < 4; nt++) {
                    int n = n0 + wn * 32 + nt * 8 + tig * 2;
                    float h0 = acc[mt][nt][half * 2 + 0];
                    float h1 = acc[mt][nt][half * 2 + 1];
                    float a0 = (h0 > 0.0f) ? wt * h0 * h0 : 0.0f;
                    float a1 = (h1 > 0.0f) ? wt * h1 * h1 : 0.0f;
                    __nv_bfloat16 hi0 = __float2bfloat16(a0);
                    __nv_bfloat16 hi1 = __float2bfloat16(a1);
                    __nv_bfloat16 lo0 = __float2bfloat16(a0 - __bfloat162float(hi0));
                    __nv_bfloat16 lo1 = __float2bfloat16(a1 - __bfloat162float(hi1));
                    __nv_bfloat162 hh; hh.x = hi0; hh.y = hi1;
                    __nv_bfloat162 ll; ll.x = lo0; ll.y = lo1;
                    *(__nv_bfloat162*)(dst + n)        = hh;
                    *(__nv_bfloat162*)(dst + 1024 + n) = hh;
                    *(__nv_bfloat162*)(dst + 2048 + n) = ll;
                }
            } else {
                int tok = tok_s[ml];
                float* orow = out + (size_t)tok * D_DIM;
#pragma unroll
                for (int nt = 0; nt < 4; nt++) {
                    int n = n0 + wn * 32 + nt * 8 + tig * 2;
                    atomicAdd(&orow[n],     acc[mt][nt][half * 2 + 0]);
                    atomicAdd(&orow[n + 1], acc[mt][nt][half * 2 + 1]);
                }
            }
        }
    }
}

// ---------------- launch ------------------------------------------------------
extern "C" void kernel_launch(void* const* d_in, const int* in_sizes, int n_in,
                              void* d_out, int out_size) {
    const float* x  = (const float*)d_in[0];   // [2,2048,1024]
    const float* rw = (const float*)d_in[1];   // [8,1024]
    const float* w1 = (const float*)d_in[2];   // [1024, 8192]
    const float* w2 = (const float*)d_in[3];   // [8192, 1024]
    float* out = (float*)d_out;

    zero_kernel<<<(T_TOK * D_DIM + 255) / 256, 256>>>(out);
    convert_x<<<(T_TOK * D_DIM + 255) / 256, 256>>>(x);

    dim3 tg(32, 32, E_NUM), tb(32, 8);
    convert_w<<<tg, tb>>>(w1, 0);
    convert_w<<<tg, tb>>>(w2, 1);

    router_kernel<<<(T_TOK * 32 + 255) / 256, 256>>>(x, rw);
    offsets_kernel<<<1, 32>>>();
    fill_kernel<<<(T_TOK + 255) / 256, 256>>>();

    dim3 gup(W_DIM / 128, T_TOK / 128, E_NUM);   // (8, 32, 8)
    moe_gemm<0><<<gup, 256>>>(out);
    dim3 gdn(D_DIM / 128, T_TOK / 128, E_NUM);   // (8, 32, 8)
    moe_gemm<1><<<gdn, 256>>>(out);
}

// round 11
// speedup vs baseline: 1.6381x; 1.0336x over previous
#include <cuda_runtime.h>
#include <cuda_bf16.h>
#include <math.h>
#include <stdint.h>

// ---------------- problem constants ----------------------------------------
#define T_TOK 4096
#define D_DIM 1024
#define E_NUM 8
#define W_DIM 1024
#define SLOTS 8192          // T*2 (top-2)
#define K3    3072          // weights/x: A=[hi|hi|lo], B=[hi|lo|hi] concatenated
#define K2    2048          // activations: [hi|lo] stored, chunk-remapped on read
#define BK    32
#define NCH   (K3 / BK)     // 96
#define SAS   40            // smem row stride (bf16) -> conflict-free frag LDS

// ---------------- device scratch --------------------------------------------
__device__ int   g_count[E_NUM];
__device__ int   g_fill [E_NUM];
__device__ int   g_off  [E_NUM + 1];
__device__ int   g_sel  [T_TOK * 2];
__device__ float g_selw [T_TOK * 2];
__device__ int   g_tok  [SLOTS];
__device__ float g_wt   [SLOTS];
__device__ __nv_bfloat16 g_xcat [(size_t)T_TOK * K3];          // 25 MB
__device__ __nv_bfloat16 g_w1cat[(size_t)E_NUM * W_DIM * K3];  // 50 MB [e][n][k]
__device__ __nv_bfloat16 g_w2cat[(size_t)E_NUM * D_DIM * K3];  // 50 MB [e][d][k]
__device__ __nv_bfloat16 g_acat [(size_t)SLOTS * K2];          // 33.5 MB [slot][hi|lo]

// chunk -> stored-K offset for the deduped activation buffer ([hi|hi|lo] read)
__device__ __forceinline__ int kbA2(int c) {
    return (c < 32) ? c * 32 : (c < 64 ? (c - 32) * 32 : c * 32 - 1024);
}

// ---------------- fused pre-pass: zero out + x split + router ---------------
__global__ void zcnt_kernel() {
    if (threadIdx.x < E_NUM) { g_count[threadIdx.x] = 0; g_fill[threadIdx.x] = 0; }
}

__global__ void __launch_bounds__(128) pre_x(const float* __restrict__ x,
                                             const float* __restrict__ rw,
                                             float* __restrict__ out) {
    __shared__ float wsum[4][E_NUM];
    int t = blockIdx.x;
    int tid = threadIdx.x, lane = tid & 31, wrp = tid >> 5;
    const float* xr = x + (size_t)t * D_DIM;
    int d0 = tid * 8;

    // load 8 elems
    float4 v0 = *(const float4*)(xr + d0);
    float4 v1 = *(const float4*)(xr + d0 + 4);
    float xv[8] = { v0.x, v0.y, v0.z, v0.w, v1.x, v1.y, v1.z, v1.w };

    // zero the output row
    float4 z = make_float4(0.f, 0.f, 0.f, 0.f);
    *(float4*)(out + (size_t)t * D_DIM + d0)     = z;
    *(float4*)(out + (size_t)t * D_DIM + d0 + 4) = z;

    // split + store xcat [hi|hi|lo]
    size_t b = (size_t)t * K3;
    __nv_bfloat16 hi8[8], lo8[8];
#pragma unroll
    for (int i = 0; i < 8; i++) {
        hi8[i] = __float2bfloat16(xv[i]);
        lo8[i] = __float2bfloat16(xv[i] - __bfloat162float(hi8[i]));
    }
    *(uint4*)(&g_xcat[b + d0])        = *(uint4*)hi8;
    *(uint4*)(&g_xcat[b + 1024 + d0]) = *(uint4*)hi8;
    *(uint4*)(&g_xcat[b + 2048 + d0]) = *(uint4*)lo8;

    // router partials: 8 experts x 8 elems
    float p[E_NUM];
#pragma unroll
    for (int e = 0; e < E_NUM; e++) {
        const float* wr = rw + e * D_DIM + d0;
        float s = 0.f;
#pragma unroll
        for (int i = 0; i < 8; i++) s += xv[i] * wr[i];
        p[e] = s;
    }
#pragma unroll
    for (int e = 0; e < E_NUM; e++)
#pragma unroll
        for (int o = 16; o; o >>= 1) p[e] += __shfl_xor_sync(0xffffffffu, p[e], o);
    if (lane == 0)
#pragma unroll
        for (int e = 0; e < E_NUM; e++) wsum[wrp][e] = p[e];
    __syncthreads();
    if (tid == 0) {
        float q[E_NUM];
#pragma unroll
        for (int e = 0; e < E_NUM; e++)
            q[e] = wsum[0][e] + wsum[1][e] + wsum[2][e] + wsum[3][e];
        int i1 = 0; float v1 = q[0];
#pragma unroll
        for (int e = 1; e < E_NUM; e++) if (q[e] > v1) { v1 = q[e]; i1 = e; }
        int i2 = -1; float v2 = -3.0e38f;
#pragma unroll
        for (int e = 0; e < E_NUM; e++) if (e != i1 && q[e] > v2) { v2 = q[e]; i2 = e; }
        float p1 = 1.0f / (1.0f + expf(-v1));
        float p2 = 1.0f / (1.0f + expf(-v2));
        float s = p1 + p2 + 1e-20f;
        g_sel [t * 2 + 0] = i1;  g_sel [t * 2 + 1] = i2;
        g_selw[t * 2 + 0] = p1 / s;
        g_selw[t * 2 + 1] = p2 / s;
        atomicAdd(&g_count[i1], 1);
        atomicAdd(&g_count[i2], 1);
    }
}

__global__ void offsets_kernel() {
    if (threadIdx.x == 0 && blockIdx.x == 0) {
        int s = 0;
#pragma unroll
        for (int e = 0; e < E_NUM; e++) { g_off[e] = s; s += g_count[e]; }
        g_off[E_NUM] = s;
    }
}

__global__ void fill_kernel() {
    int t = blockIdx.x * blockDim.x + threadIdx.x;
    if (t >= T_TOK) return;
#pragma unroll
    for (int k = 0; k < 2; k++) {
        int e = g_sel[t * 2 + k];
        int pos = g_off[e] + atomicAdd(&g_fill[e], 1);
        g_tok[pos] = t;
        g_wt [pos] = g_selw[t * 2 + k];
    }
}

// Per-expert 1024x1024 transpose + split: dst[e][n][k-seg], segs [hi|lo|hi]
// blockIdx.z: bits [0:3)=expert, bit 3=sel (0:w1, 1:w2)
__global__ void convert_w(const float* __restrict__ w1, const float* __restrict__ w2) {
    __shared__ float tile[32][33];
    int sel = blockIdx.z >> 3;
    int e   = blockIdx.z & 7;
    int r0 = blockIdx.y * 32, c0 = blockIdx.x * 32;
    const float* src = sel ? w2 : w1;
    int src_ld  = sel ? 1024 : 8192;
    int row_off = sel ? e * 1024 : 0;
    int col_off = sel ? 0 : e * 1024;
    const float* s = src + (size_t)(row_off + r0) * src_ld + col_off + c0;
#pragma unroll
    for (int i = threadIdx.y; i < 32; i += 8)
        tile[i][threadIdx.x] = s[(size_t)i * src_ld + threadIdx.x];
    __syncthreads();
    __nv_bfloat16* d = (sel ? g_w2cat : g_w1cat) + (size_t)e * 1024 * K3;
#pragma unroll
    for (int i = threadIdx.y; i < 32; i += 8) {
        int c = c0 + i;               // dst row (N index)
        int r = r0 + threadIdx.x;     // dst col (K index)
        float v = tile[threadIdx.x][i];
        __nv_bfloat16 hi = __float2bfloat16(v);
        __nv_bfloat16 lo = __float2bfloat16(v - __bfloat162float(hi));
        size_t bi = (size_t)c * K3 + r;
        d[bi] = hi; d[bi + 1024] = lo; d[bi + 2048] = hi;
    }
}

// ---------------- mma.sync helper -------------------------------------------
__device__ __forceinline__ void mma16816(float* d, const uint32_t* a, const uint32_t* b) {
    asm volatile(
        "mma.sync.aligned.m16n8k16.row.col.f32.bf16.bf16.f32 "
        "{%0,%1,%2,%3}, {%4,%5,%6,%7}, {%8,%9}, {%0,%1,%2,%3};"
        : "+f"(d[0]), "+f"(d[1]), "+f"(d[2]), "+f"(d[3])
        : "r"(a[0]), "r"(a[1]), "r"(a[2]), "r"(a[3]), "r"(b[0]), "r"(b[1]));
}

// ---------------- grouped GEMM (HMMA via mma.sync, bf16x3, 2 CTA/SM) --------
// MODE 0: up-proj  (A = g_xcat [K3] by token, B = g_w1cat, epi -> g_acat [hi|lo])
// MODE 1: down-proj(A = g_acat [K2] chunk-remapped, B = g_w2cat, epi -> atomicAdd)
template <int MODE>
__global__ void __launch_bounds__(256, 2) moe_gemm(float* __restrict__ out) {
    __shared__ __nv_bfloat16 As[2][128][SAS];
    __shared__ __nv_bfloat16 Bs[2][128][SAS];
    __shared__ int   tok_s[128];
    __shared__ float wt_s [128];

    int e = blockIdx.z;
    int cnt = g_count[e];
    int m0 = blockIdx.y * 128;
    if (m0 >= cnt) return;
    int base = g_off[e];
    int n0 = blockIdx.x * 128;

    int tid = threadIdx.x, lane = tid & 31, wid = tid >> 5;
    int wm = wid & 1, wn = wid >> 1;        // warp grid 2 x 4 -> 64 x 32 per warp
    int g = lane >> 2, tig = lane & 3;

    if (tid < 128) {
        int slot = base + m0 + tid; if (slot >= SLOTS) slot = SLOTS - 1;
        tok_s[tid] = g_tok[slot];
        wt_s [tid] = g_wt[slot];
    }
    __syncthreads();

    // global load assignment: 512 uint4 per tile, 2 per thread (rows r, r+64)
    int arow0 = tid >> 2, arow1 = arow0 + 64;
    int aseg  = (tid & 3) * 8;
    const __nv_bfloat16 *Ab0, *Ab1;
    if (MODE == 0) {
        Ab0 = g_xcat + (size_t)tok_s[arow0] * K3 + aseg;
        Ab1 = g_xcat + (size_t)tok_s[arow1] * K3 + aseg;
    } else {
        int s0 = base + m0 + arow0; if (s0 >= SLOTS) s0 = SLOTS - 1;
        int s1 = base + m0 + arow1; if (s1 >= SLOTS) s1 = SLOTS - 1;
        Ab0 = g_acat + (size_t)s0 * K2 + aseg;
        Ab1 = g_acat + (size_t)s1 * K2 + aseg;
    }
    const __nv_bfloat16* Bexp = (MODE ? g_w2cat : g_w1cat) + (size_t)e * 1024 * K3;
    const __nv_bfloat16* Bb0 = Bexp + (size_t)(n0 + arow0) * K3 + aseg;
    const __nv_bfloat16* Bb1 = Bexp + (size_t)(n0 + arow1) * K3 + aseg;

    float acc[4][4][4];
#pragma unroll
    for (int i = 0; i < 4; i++)
#pragma unroll
        for (int j = 0; j < 4; j++)
#pragma unroll
            for (int q = 0; q < 4; q++) acc[i][j][q] = 0.0f;

    // prologue: chunk 0 -> stage 0 (kbA2(0)=0 for MODE 1)
    {
        uint4 a0 = *(const uint4*)(Ab0);
        uint4 a1 = *(const uint4*)(Ab1);
        uint4 b0 = *(const uint4*)(Bb0);
        uint4 b1 = *(const uint4*)(Bb1);
        *(uint4*)&As[0][arow0][aseg] = a0;
        *(uint4*)&As[0][arow1][aseg] = a1;
        *(uint4*)&Bs[0][arow0][aseg] = b0;
        *(uint4*)&Bs[0][arow1][aseg] = b1;
    }
    __syncthreads();

#pragma unroll 1
    for (int c = 0; c < NCH; c++) {
        int s = c & 1;
        int d = s ^ 1;
        bool pf = (c + 1 < NCH);
        int kn  = (c + 1) * BK;
        int knA = (MODE == 1) ? kbA2(c + 1) : kn;

        // ---- phase A-prefetch ----
        uint4 pa0, pa1;
        if (pf) {
            pa0 = *(const uint4*)(Ab0 + knA);
            pa1 = *(const uint4*)(Ab1 + knA);
        }
        // ---- ks = 0: frags + MMA ----
        {
            const int kc = 0;
            uint32_t bfr[4][2];
#pragma unroll
            for (int nt = 0; nt < 4; nt++) {
                int rb = wn * 32 + nt * 8 + g;
                bfr[nt][0] = *(const uint32_t*)&Bs[s][rb][kc + tig * 2];
                bfr[nt][1] = *(const uint32_t*)&Bs[s][rb][kc + tig * 2 + 8];
            }
#pragma unroll
            for (int mt = 0; mt < 4; mt++) {
                uint32_t af[4];
                int r = wm * 64 + mt * 16 + g;
                af[0] = *(const uint32_t*)&As[s][r    ][kc + tig * 2];
                af[1] = *(const uint32_t*)&As[s][r + 8][kc + tig * 2];
                af[2] = *(const uint32_t*)&As[s][r    ][kc + tig * 2 + 8];
                af[3] = *(const uint32_t*)&As[s][r + 8][kc + tig * 2 + 8];
#pragma unroll
                for (int nt = 0; nt < 4; nt++)
                    mma16816(acc[mt][nt], af, bfr[nt]);
            }
        }
        // ---- store A-prefetch, fetch B-prefetch ----
        uint4 pb0, pb1;
        if (pf) {
            *(uint4*)&As[d][arow0][aseg] = pa0;
            *(uint4*)&As[d][arow1][aseg] = pa1;
            pb0 = *(const uint4*)(Bb0 + kn);
            pb1 = *(const uint4*)(Bb1 + kn);
        }
        // ---- ks = 1: frags + MMA ----
        {
            const int kc = 16;
            uint32_t bfr[4][2];
#pragma unroll
            for (int nt = 0; nt < 4; nt++) {
                int rb = wn * 32 + nt * 8 + g;
                bfr[nt][0] = *(const uint32_t*)&Bs[s][rb][kc + tig * 2];
                bfr[nt][1] = *(const uint32_t*)&Bs[s][rb][kc + tig * 2 + 8];
            }
#pragma unroll
            for (int mt = 0; mt < 4; mt++) {
                uint32_t af[4];
                int r = wm * 64 + mt * 16 + g;
                af[0] = *(const uint32_t*)&As[s][r    ][kc + tig * 2];
                af[1] = *(const uint32_t*)&As[s][r + 8][kc + tig * 2];
                af[2] = *(const uint32_t*)&As[s][r    ][kc + tig * 2 + 8];
                af[3] = *(const uint32_t*)&As[s][r + 8][kc + tig * 2 + 8];
#pragma unroll
                for (int nt = 0; nt < 4; nt++)
                    mma16816(acc[mt][nt], af, bfr[nt]);
            }
        }
        // ---- store B-prefetch ----
        if (pf) {
            *(uint4*)&Bs[d][arow0][aseg] = pb0;
            *(uint4*)&Bs[d][arow1][aseg] = pb1;
        }
        __syncthreads();
    }

    // ---------------- epilogue ----------------
#pragma unroll
    for (int mt = 0; mt < 4; mt++) {
#pragma unroll
        for (int half = 0; half < 2; half++) {
            int ml = wm * 64 + mt * 16 + g + half * 8;   // local row 0..127
            int m = m0 + ml;
            if (m >= cnt) continue;
            if (MODE == 0) {
                int slot = base + m;
                float wt = wt_s[ml];
                __nv_bfloat16* dst = g_acat + (size_t)slot * K2;
#pragma unroll
                for (int nt = 0; nt < 4; nt++) {
                    int n = n0 + wn * 32 + nt * 8 + tig * 2;
                    float h0 = acc[mt][nt][half * 2 + 0];
                    float h1 = acc[mt][nt][half * 2 + 1];
                    float a0 = (h0 > 0.0f) ? wt * h0 * h0 : 0.0f;
                    float a1 = (h1 > 0.0f) ? wt * h1 * h1 : 0.0f;
                    __nv_bfloat16 hi0 = __float2bfloat16(a0);
                    __nv_bfloat16 hi1 = __float2bfloat16(a1);
                    __nv_bfloat16 lo0 = __float2bfloat16(a0 - __bfloat162float(hi0));
                    __nv_bfloat16 lo1 = __float2bfloat16(a1 - __bfloat162float(hi1));
                    __nv_bfloat162 hh; hh.x = hi0; hh.y = hi1;
                    __nv_bfloat162 ll; ll.x = lo0; ll.y = lo1;
                    *(__nv_bfloat162*)(dst + n)        = hh;
                    *(__nv_bfloat162*)(dst + 1024 + n) = ll;
                }
            } else {
                int tok = tok_s[ml];
                float* orow = out + (size_t)tok * D_DIM;
#pragma unroll
                for (int nt = 0; nt < 4; nt++) {
                    int n = n0 + wn * 32 + nt * 8 + tig * 2;
                    atomicAdd(&orow[n],     acc[mt][nt][half * 2 + 0]);
                    atomicAdd(&orow[n + 1], acc[mt][nt][half * 2 + 1]);
                }
            }
        }
    }
}

// ---------------- launch ------------------------------------------------------
extern "C" void kernel_launch(void* const* d_in, const int* in_sizes, int n_in,
                              void* d_out, int out_size) {
    const float* x  = (const float*)d_in[0];   // [2,2048,1024]
    const float* rw = (const float*)d_in[1];   // [8,1024]
    const float* w1 = (const float*)d_in[2];   // [1024, 8192]
    const float* w2 = (const float*)d_in[3];   // [8192, 1024]
    float* out = (float*)d_out;

    zcnt_kernel<<<1, 32>>>();
    pre_x<<<T_TOK, 128>>>(x, rw, out);

    dim3 tg(32, 32, 16), tb(32, 8);
    convert_w<<<tg, tb>>>(w1, w2);

    offsets_kernel<<<1, 32>>>();
    fill_kernel<<<(T_TOK + 255) / 256, 256>>>();

    dim3 gup(W_DIM / 128, T_TOK / 128, E_NUM);   // (8, 32, 8)
    moe_gemm<0><<<gup, 256>>>(out);
    dim3 gdn(D_DIM / 128, T_TOK / 128, E_NUM);   // (8, 32, 8)
    moe_gemm<1><<<gdn, 256>>>(out);
}

// round 12
// speedup vs baseline: 1.6814x; 1.0264x over previous
#include <cuda_runtime.h>
#include <cuda_bf16.h>
#include <math.h>
#include <stdint.h>

// ---------------- problem constants ----------------------------------------
#define T_TOK 4096
#define D_DIM 1024
#define E_NUM 8
#define W_DIM 1024
#define CAP   4096          // per-expert slot capacity (overflow-proof)
#define K3    3072          // weights/x: A=[hi|hi|lo], B=[hi|lo|hi] concatenated
#define K2    2048          // activations: [hi|lo] stored, chunk-remapped on read
#define BK    32
#define NCH   (K3 / BK)     // 96
#define SAS   40            // smem row stride (bf16) -> conflict-free frag LDS

// ---------------- device scratch --------------------------------------------
__device__ int   g_fill[E_NUM];
__device__ int   g_tok [E_NUM * CAP];
__device__ float g_wt  [E_NUM * CAP];
__device__ __nv_bfloat16 g_xcat [(size_t)T_TOK * K3];           // 25 MB
__device__ __nv_bfloat16 g_w1cat[(size_t)E_NUM * W_DIM * K3];   // 50 MB [e][n][k]
__device__ __nv_bfloat16 g_w2cat[(size_t)E_NUM * D_DIM * K3];   // 50 MB [e][d][k]
__device__ __nv_bfloat16 g_acat [(size_t)E_NUM * CAP * K2];     // 134 MB [slot][hi|lo]

// chunk -> stored-K offset for the deduped activation buffer ([hi|hi|lo] read)
__device__ __forceinline__ int kbA2(int c) {
    return (c < 32) ? c * 32 : (c < 64 ? (c - 32) * 32 : c * 32 - 1024);
}

// ---------------- pre-pass ---------------------------------------------------
__global__ void zcnt_kernel() {
    if (threadIdx.x < E_NUM) g_fill[threadIdx.x] = 0;
}

// fused: zero out + x split + router + slot assignment
__global__ void __launch_bounds__(128) pre_x(const float* __restrict__ x,
                                             const float* __restrict__ rw,
                                             float* __restrict__ out) {
    __shared__ float wsum[4][E_NUM];
    int t = blockIdx.x;
    int tid = threadIdx.x, lane = tid & 31, wrp = tid >> 5;
    const float* xr = x + (size_t)t * D_DIM;
    int d0 = tid * 8;

    float4 v0 = *(const float4*)(xr + d0);
    float4 v1 = *(const float4*)(xr + d0 + 4);
    float xv[8] = { v0.x, v0.y, v0.z, v0.w, v1.x, v1.y, v1.z, v1.w };

    // zero the output row
    float4 z = make_float4(0.f, 0.f, 0.f, 0.f);
    *(float4*)(out + (size_t)t * D_DIM + d0)     = z;
    *(float4*)(out + (size_t)t * D_DIM + d0 + 4) = z;

    // split + store xcat [hi|hi|lo]
    size_t b = (size_t)t * K3;
    __nv_bfloat16 hi8[8], lo8[8];
#pragma unroll
    for (int i = 0; i < 8; i++) {
        hi8[i] = __float2bfloat16(xv[i]);
        lo8[i] = __float2bfloat16(xv[i] - __bfloat162float(hi8[i]));
    }
    *(uint4*)(&g_xcat[b + d0])        = *(uint4*)hi8;
    *(uint4*)(&g_xcat[b + 1024 + d0]) = *(uint4*)hi8;
    *(uint4*)(&g_xcat[b + 2048 + d0]) = *(uint4*)lo8;

    // router partials
    float p[E_NUM];
#pragma unroll
    for (int e = 0; e < E_NUM; e++) {
        const float* wr = rw + e * D_DIM + d0;
        float s = 0.f;
#pragma unroll
        for (int i = 0; i < 8; i++) s += xv[i] * wr[i];
        p[e] = s;
    }
#pragma unroll
    for (int e = 0; e < E_NUM; e++)
#pragma unroll
        for (int o = 16; o; o >>= 1) p[e] += __shfl_xor_sync(0xffffffffu, p[e], o);
    if (lane == 0)
#pragma unroll
        for (int e = 0; e < E_NUM; e++) wsum[wrp][e] = p[e];
    __syncthreads();
    if (tid == 0) {
        float q[E_NUM];
#pragma unroll
        for (int e = 0; e < E_NUM; e++)
            q[e] = wsum[0][e] + wsum[1][e] + wsum[2][e] + wsum[3][e];
        int i1 = 0; float v1 = q[0];
#pragma unroll
        for (int e = 1; e < E_NUM; e++) if (q[e] > v1) { v1 = q[e]; i1 = e; }
        int i2 = -1; float v2 = -3.0e38f;
#pragma unroll
        for (int e = 0; e < E_NUM; e++) if (e != i1 && q[e] > v2) { v2 = q[e]; i2 = e; }
        float p1 = 1.0f / (1.0f + expf(-v1));
        float p2 = 1.0f / (1.0f + expf(-v2));
        float s = p1 + p2 + 1e-20f;
        // direct slot assignment (capacity layout; no offsets pass needed)
        int pos1 = atomicAdd(&g_fill[i1], 1);
        g_tok[i1 * CAP + pos1] = t;
        g_wt [i1 * CAP + pos1] = p1 / s;
        int pos2 = atomicAdd(&g_fill[i2], 1);
        g_tok[i2 * CAP + pos2] = t;
        g_wt [i2 * CAP + pos2] = p2 / s;
    }
}

// Per-expert 1024x1024 transpose + split: dst[e][n][k-seg], segs [hi|lo|hi]
// blockIdx.z: bits [0:3)=expert, bit 3=sel (0:w1, 1:w2)
__global__ void convert_w(const float* __restrict__ w1, const float* __restrict__ w2) {
    __shared__ float tile[32][33];
    int sel = blockIdx.z >> 3;
    int e   = blockIdx.z & 7;
    int r0 = blockIdx.y * 32, c0 = blockIdx.x * 32;
    const float* src = sel ? w2 : w1;
    int src_ld  = sel ? 1024 : 8192;
    int row_off = sel ? e * 1024 : 0;
    int col_off = sel ? 0 : e * 1024;
    const float* s = src + (size_t)(row_off + r0) * src_ld + col_off + c0;
#pragma unroll
    for (int i = threadIdx.y; i < 32; i += 8)
        tile[i][threadIdx.x] = s[(size_t)i * src_ld + threadIdx.x];
    __syncthreads();
    __nv_bfloat16* d = (sel ? g_w2cat : g_w1cat) + (size_t)e * 1024 * K3;
#pragma unroll
    for (int i = threadIdx.y; i < 32; i += 8) {
        int c = c0 + i;               // dst row (N index)
        int r = r0 + threadIdx.x;     // dst col (K index)
        float v = tile[threadIdx.x][i];
        __nv_bfloat16 hi = __float2bfloat16(v);
        __nv_bfloat16 lo = __float2bfloat16(v - __bfloat162float(hi));
        size_t bi = (size_t)c * K3 + r;
        d[bi] = hi; d[bi + 1024] = lo; d[bi + 2048] = hi;
    }
}

// ---------------- mma.sync helper -------------------------------------------
__device__ __forceinline__ void mma16816(float* d, const uint32_t* a, const uint32_t* b) {
    asm volatile(
        "mma.sync.aligned.m16n8k16.row.col.f32.bf16.bf16.f32 "
        "{%0,%1,%2,%3}, {%4,%5,%6,%7}, {%8,%9}, {%0,%1,%2,%3};"
        : "+f"(d[0]), "+f"(d[1]), "+f"(d[2]), "+f"(d[3])
        : "r"(a[0]), "r"(a[1]), "r"(a[2]), "r"(a[3]), "r"(b[0]), "r"(b[1]));
}

// ---------------- grouped GEMM (HMMA via mma.sync, bf16x3, 2 CTA/SM) --------
// MODE 0: up-proj  (A = g_xcat [K3] by token, B = g_w1cat, epi -> g_acat [hi|lo])
// MODE 1: down-proj(A = g_acat [K2] chunk-remapped, B = g_w2cat, epi -> atomicAdd)
template <int MODE>
__global__ void __launch_bounds__(256, 2) moe_gemm(float* __restrict__ out) {
    __shared__ __nv_bfloat16 As[2][128][SAS];
    __shared__ __nv_bfloat16 Bs[2][128][SAS];
    __shared__ int   tok_s[128];
    __shared__ float wt_s [128];

    int e = blockIdx.z;
    int cnt = g_fill[e];
    int m0 = blockIdx.y * 128;
    if (m0 >= cnt) return;
    int base = e * CAP;
    int n0 = blockIdx.x * 128;

    int tid = threadIdx.x, lane = tid & 31, wid = tid >> 5;
    int wm = wid & 1, wn = wid >> 1;        // warp grid 2 x 4 -> 64 x 32 per warp
    int g = lane >> 2, tig = lane & 3;

    if (tid < 128) {
        int m = m0 + tid;
        // sanitize rows beyond cnt (their g_tok/g_acat entries are uninitialized)
        tok_s[tid] = (m < cnt) ? g_tok[base + m] : 0;
        wt_s [tid] = (m < cnt) ? g_wt [base + m] : 0.0f;
    }
    __syncthreads();

    // global load assignment: 512 uint4 per tile, 2 per thread (rows r, r+64)
    int arow0 = tid >> 2, arow1 = arow0 + 64;
    int aseg  = (tid & 3) * 8;
    const __nv_bfloat16 *Ab0, *Ab1;
    if (MODE == 0) {
        Ab0 = g_xcat + (size_t)tok_s[arow0] * K3 + aseg;
        Ab1 = g_xcat + (size_t)tok_s[arow1] * K3 + aseg;
    } else {
        // contiguous slots; rows beyond cnt read stale data, discarded in epilogue
        Ab0 = g_acat + (size_t)(base + m0 + arow0) * K2 + aseg;
        Ab1 = g_acat + (size_t)(base + m0 + arow1) * K2 + aseg;
    }
    const __nv_bfloat16* Bexp = (MODE ? g_w2cat : g_w1cat) + (size_t)e * 1024 * K3;
    const __nv_bfloat16* Bb0 = Bexp + (size_t)(n0 + arow0) * K3 + aseg;
    const __nv_bfloat16* Bb1 = Bexp + (size_t)(n0 + arow1) * K3 + aseg;

    float acc[4][4][4];
#pragma unroll
    for (int i = 0; i < 4; i++)
#pragma unroll
        for (int j = 0; j < 4; j++)
#pragma unroll
            for (int q = 0; q < 4; q++) acc[i][j][q] = 0.0f;

    // prologue: chunk 0 -> stage 0 (kbA2(0)=0 for MODE 1)
    {
        uint4 a0 = *(const uint4*)(Ab0);
        uint4 a1 = *(const uint4*)(Ab1);
        uint4 b0 = *(const uint4*)(Bb0);
        uint4 b1 = *(const uint4*)(Bb1);
        *(uint4*)&As[0][arow0][aseg] = a0;
        *(uint4*)&As[0][arow1][aseg] = a1;
        *(uint4*)&Bs[0][arow0][aseg] = b0;
        *(uint4*)&Bs[0][arow1][aseg] = b1;
    }
    __syncthreads();

#pragma unroll 1
    for (int c = 0; c < NCH; c++) {
        int s = c & 1;
        int d = s ^ 1;
        bool pf = (c + 1 < NCH);
        int kn  = (c + 1) * BK;
        int knA = (MODE == 1) ? kbA2(c + 1) : kn;

        // ---- phase A-prefetch ----
        uint4 pa0, pa1;
        if (pf) {
            pa0 = *(const uint4*)(Ab0 + knA);
            pa1 = *(const uint4*)(Ab1 + knA);
        }
        // ---- ks = 0: frags + MMA ----
        {
            const int kc = 0;
            uint32_t bfr[4][2];
#pragma unroll
            for (int nt = 0; nt < 4; nt++) {
                int rb = wn * 32 + nt * 8 + g;
                bfr[nt][0] = *(const uint32_t*)&Bs[s][rb][kc + tig * 2];
                bfr[nt][1] = *(const uint32_t*)&Bs[s][rb][kc + tig * 2 + 8];
            }
#pragma unroll
            for (int mt = 0; mt < 4; mt++) {
                uint32_t af[4];
                int r = wm * 64 + mt * 16 + g;
                af[0] = *(const uint32_t*)&As[s][r    ][kc + tig * 2];
                af[1] = *(const uint32_t*)&As[s][r + 8][kc + tig * 2];
                af[2] = *(const uint32_t*)&As[s][r    ][kc + tig * 2 + 8];
                af[3] = *(const uint32_t*)&As[s][r + 8][kc + tig * 2 + 8];
#pragma unroll
                for (int nt = 0; nt < 4; nt++)
                    mma16816(acc[mt][nt], af, bfr[nt]);
            }
        }
        // ---- store A-prefetch, fetch B-prefetch ----
        uint4 pb0, pb1;
        if (pf) {
            *(uint4*)&As[d][arow0][aseg] = pa0;
            *(uint4*)&As[d][arow1][aseg] = pa1;
            pb0 = *(const uint4*)(Bb0 + kn);
            pb1 = *(const uint4*)(Bb1 + kn);
        }
        // ---- ks = 1: frags + MMA ----
        {
            const int kc = 16;
            uint32_t bfr[4][2];
#pragma unroll
            for (int nt = 0; nt < 4; nt++) {
                int rb = wn * 32 + nt * 8 + g;
                bfr[nt][0] = *(const uint32_t*)&Bs[s][rb][kc + tig * 2];
                bfr[nt][1] = *(const uint32_t*)&Bs[s][rb][kc + tig * 2 + 8];
            }
#pragma unroll
            for (int mt = 0; mt < 4; mt++) {
                uint32_t af[4];
                int r = wm * 64 + mt * 16 + g;
                af[0] = *(const uint32_t*)&As[s][r    ][kc + tig * 2];
                af[1] = *(const uint32_t*)&As[s][r + 8][kc + tig * 2];
                af[2] = *(const uint32_t*)&As[s][r    ][kc + tig * 2 + 8];
                af[3] = *(const uint32_t*)&As[s][r + 8][kc + tig * 2 + 8];
#pragma unroll
                for (int nt = 0; nt < 4; nt++)
                    mma16816(acc[mt][nt], af, bfr[nt]);
            }
        }
        // ---- store B-prefetch ----
        if (pf) {
            *(uint4*)&Bs[d][arow0][aseg] = pb0;
            *(uint4*)&Bs[d][arow1][aseg] = pb1;
        }
        __syncthreads();
    }

    // ---------------- epilogue ----------------
#pragma unroll
    for (int mt = 0; mt < 4; mt++) {
#pragma unroll
        for (int half = 0; half < 2; half++) {
            int ml = wm * 64 + mt * 16 + g + half * 8;   // local row 0..127
            int m = m0 + ml;
            if (m >= cnt) continue;
            if (MODE == 0) {
                float wt = wt_s[ml];
                __nv_bfloat16* dst = g_acat + (size_t)(base + m) * K2;
#pragma unroll
                for (int nt = 0; nt < 4; nt++) {
                    int n = n0 + wn * 32 + nt * 8 + tig * 2;
                    float h0 = acc[mt][nt][half * 2 + 0];
                    float h1 = acc[mt][nt][half * 2 + 1];
                    float a0 = (h0 > 0.0f) ? wt * h0 * h0 : 0.0f;
                    float a1 = (h1 > 0.0f) ? wt * h1 * h1 : 0.0f;
                    __nv_bfloat16 hi0 = __float2bfloat16(a0);
                    __nv_bfloat16 hi1 = __float2bfloat16(a1);
                    __nv_bfloat16 lo0 = __float2bfloat16(a0 - __bfloat162float(hi0));
                    __nv_bfloat16 lo1 = __float2bfloat16(a1 - __bfloat162float(hi1));
                    __nv_bfloat162 hh; hh.x = hi0; hh.y = hi1;
                    __nv_bfloat162 ll; ll.x = lo0; ll.y = lo1;
                    *(__nv_bfloat162*)(dst + n)        = hh;
                    *(__nv_bfloat162*)(dst + 1024 + n) = ll;
                }
            } else {
                int tok = tok_s[ml];
                float* orow = out + (size_t)tok * D_DIM;
#pragma unroll
                for (int nt = 0; nt < 4; nt++) {
                    int n = n0 + wn * 32 + nt * 8 + tig * 2;
                    atomicAdd(&orow[n],     acc[mt][nt][half * 2 + 0]);
                    atomicAdd(&orow[n + 1], acc[mt][nt][half * 2 + 1]);
                }
            }
        }
    }
}

// ---------------- launch ------------------------------------------------------
extern "C" void kernel_launch(void* const* d_in, const int* in_sizes, int n_in,
                              void* d_out, int out_size) {
    const float* x  = (const float*)d_in[0];   // [2,2048,1024]
    const float* rw = (const float*)d_in[1];   // [8,1024]
    const float* w1 = (const float*)d_in[2];   // [1024, 8192]
    const float* w2 = (const float*)d_in[3];   // [8192, 1024]
    float* out = (float*)d_out;

    zcnt_kernel<<<1, 32>>>();
    pre_x<<<T_TOK, 128>>>(x, rw, out);

    dim3 tg(32, 32, 16), tb(32, 8);
    convert_w<<<tg, tb>>>(w1, w2);

    dim3 gup(W_DIM / 128, T_TOK / 128, E_NUM);   // (8, 32, 8)
    moe_gemm<0><<<gup, 256>>>(out);
    dim3 gdn(D_DIM / 128, T_TOK / 128, E_NUM);   // (8, 32, 8)
    moe_gemm<1><<<gdn, 256>>>(out);
}